// round 6
// baseline (speedup 1.0000x reference)
#include <cuda_runtime.h>
#include <math.h>

// Problem constants
#define BATCH 128
#define TLEN 160000

// Decomposition (small regions -> high occupancy -> deep memory pipeline)
#define CHUNK 25                  // samples per thread (odd -> conflict-free smem stride)
#define NTHREADS 128              // threads per block
#define REGION (CHUNK * NTHREADS) // 3200 samples per block
#define WARM 16                   // warmup steps: per-parity decay 0.1716^8 ~ 7.5e-7
#define SMEM_FLOATS (REGION + WARM)   // 3216 floats = 12864 bytes
#define BLOCKS_PER_CH (TLEN / REGION) // 50
#define NBLOCKS (BATCH * BLOCKS_PER_CH) // 6400

// Biquad with cutoff = fs/4: cos(w0)=0 => a1=0 exactly (|a1|~7e-17 in double).
// y[n] = b0*(x[n] + x[n-2]) + b1*x[n-1] - a2*y[n-2]
// Even/odd chains decouple -> 1 dependent FFMA per 2 samples.

__global__ void __launch_bounds__(NTHREADS)
biquad_kernel(const float* __restrict__ x, float* __restrict__ y,
              float b0, float b1, float a2)
{
    extern __shared__ float s[];  // [WARM halo | REGION samples]
    const int tid = threadIdx.x;
    const int blk = blockIdx.x;
    const int ch  = blk / BLOCKS_PER_CH;
    const int s0  = (blk % BLOCKS_PER_CH) * REGION;
    const long base = (long)ch * TLEN + s0;

    // ---- Stage input: coalesced float4 loads of the 3200-sample region ----
    {
        const float4* __restrict__ xin = (const float4*)(x + base);
        float4* s4 = (float4*)(s + WARM);   // WARM=16 floats = 64B, 16B-aligned
        #pragma unroll
        for (int i = tid; i < REGION / 4; i += NTHREADS)   // 800 elems, 7 ragged iters
            s4[i] = xin[i];
        // 16-sample halo before the region (zeros at channel start == exact zero ICs)
        if (tid < WARM)
            s[tid] = (s0 == 0) ? 0.0f : x[base - WARM + tid];
    }
    __syncthreads();

    // ---- Warmup: 16 steps from zero state (smem stride 25 -> conflict-free) ----
    const int p = WARM + tid * CHUNK;
    float x1 = 0.0f, x2 = 0.0f, y1 = 0.0f, y2 = 0.0f;
    #pragma unroll
    for (int t = 0; t < WARM; ++t) {
        float xv = s[p - WARM + t];
        float fir = fmaf(b0, xv + x2, b1 * x1);   // off critical path
        float yv  = fmaf(-a2, y2, fir);           // chain: y[n] <- y[n-2]
        x2 = x1; x1 = xv;
        y2 = y1; y1 = yv;
    }
    __syncthreads();  // warmup reads (into neighbors' chunks) done before in-place writes

    // ---- Main: filter chunk in place in SMEM (unroll x2: parities pipeline) ----
    #pragma unroll
    for (int t = 0; t < CHUNK - 1; t += 2) {
        float xa = s[p + t];
        float xb = s[p + t + 1];
        float fa = fmaf(b0, xa + x2, b1 * x1);
        float ya = fmaf(-a2, y2, fa);             // even chain
        float fb = fmaf(b0, xb + x1, b1 * xa);
        float yb = fmaf(-a2, y1, fb);             // odd chain (independent)
        s[p + t]     = ya;
        s[p + t + 1] = yb;
        x2 = xa; x1 = xb;
        y2 = ya; y1 = yb;
    }
    {   // tail sample (CHUNK odd)
        float xv = s[p + CHUNK - 1];
        float fir = fmaf(b0, xv + x2, b1 * x1);
        float yv  = fmaf(-a2, y2, fir);
        s[p + CHUNK - 1] = yv;
    }
    __syncthreads();

    // ---- Store output: coalesced float4 stores ----
    {
        const float4* s4 = (const float4*)(s + WARM);
        float4* __restrict__ yout = (float4*)(y + base);
        #pragma unroll
        for (int i = tid; i < REGION / 4; i += NTHREADS)
            yout[i] = s4[i];
    }
}

extern "C" void kernel_launch(void* const* d_in, const int* in_sizes, int n_in,
                              void* d_out, int out_size)
{
    const float* x = (const float*)d_in[0];
    float* y = (float*)d_out;

    // torchaudio lowpass_biquad coefficients (double math, then float32)
    const double PI = 3.14159265358979323846;
    double w0    = 2.0 * PI * 8000.0 / 32000.0;
    double alpha = sin(w0) / (2.0 * 0.707);
    double cw    = cos(w0);           // ~6e-17: a1 term dropped (|a1*y|~1e-16)
    double b0d = (1.0 - cw) / 2.0;
    double b1d = 1.0 - cw;
    double a0d = 1.0 + alpha;
    double a2d = 1.0 - alpha;
    float b0 = (float)(b0d / a0d);
    float b1 = (float)(b1d / a0d);
    float a2 = (float)(a2d / a0d);

    biquad_kernel<<<NBLOCKS, NTHREADS, SMEM_FLOATS * sizeof(float)>>>(
        x, y, b0, b1, a2);
}